// round 5
// baseline (speedup 1.0000x reference)
#include <cuda_runtime.h>
#include <cuda_bf16.h>
#include <cstdint>

#define N_NODES 100000
#define DIM 64
#define N_EDGES 1200000
#define CAP 64                      // fixed bucket capacity per node

// ---- scratch (__device__ globals: allocation-free rule) --------------------
__device__ float g_t[N_NODES * DIM];          // neighbor-transformed features h@Wn
__device__ float g_acc[N_NODES * DIM];        // pre-activation accumulator
__device__ int   g_cnt[N_NODES];              // per-node in-degree / fill cursor
__device__ int2  g_cw[(size_t)N_NODES * CAP]; // bucketed (col, weight-bits)

// ---------------------------------------------------------------------------
// Bucketed edge build: one pass, no scan. cnt must be zeroed first.
// ---------------------------------------------------------------------------
__global__ void k_fill(const int* __restrict__ row, const int* __restrict__ col,
                       const float* __restrict__ ew)
{
    int e = blockIdx.x * blockDim.x + threadIdx.x;
    if (e >= N_EDGES) return;
    const int r = row[e];
    const int p = atomicAdd(&g_cnt[r], 1);
    if (p < CAP)
        g_cw[(size_t)r * CAP + p] = make_int2(col[e], __float_as_int(ew[e]));
}

// ---------------------------------------------------------------------------
__device__ __forceinline__ unsigned long long dup_f(float f)
{
    unsigned long long r;
    asm("mov.b64 %0, {%1,%1};" : "=l"(r) : "r"(__float_as_uint(f)));
    return r;
}
__device__ __forceinline__ void fma2(unsigned long long& acc,
                                     unsigned long long a, unsigned long long b)
{
    asm("fma.rn.f32x2 %0, %1, %2, %0;" : "+l"(acc) : "l"(a), "l"(b));
}
__device__ __forceinline__ float f_lo(unsigned long long v)
{ return __uint_as_float((uint32_t)v); }
__device__ __forceinline__ float f_hi(unsigned long long v)
{ return __uint_as_float((uint32_t)(v >> 32)); }

// ---------------------------------------------------------------------------
// K1: fused dual GEMM.  acc = relu?(in)@Ws + b ; t = relu?(in)@Wn
// (S,N) packed per f32x2 lane: acc2 += (g,g)*(ws,wn). Weights interleaved in
// SMEM -> loaded as operand with NO packing movs; node values stored
// pre-duplicated (g,g) in SMEM (two 32-k phases, 16KB each).
// 64 nodes/block; thread owns 8 nodes x 2 j. Warp = 2 node octets (broadcast
// loads) x 16 j-pairs (256B weight loads). Per k/thread: 5 LDS.128 + 16 FFMA2.
// ---------------------------------------------------------------------------
__global__ void __launch_bounds__(256, 2) sage_gemm(
    const float* __restrict__ in,
    float* __restrict__ acc,
    float* __restrict__ t,
    const float* __restrict__ Wself,
    const float* __restrict__ Wneigh,
    const float* __restrict__ bias,
    int relu_in)
{
    __shared__ float2 sW[DIM * DIM];               // 32KB, (ws,wn) at [k][j]
    __shared__ unsigned long long sgT[32 * DIM];   // 16KB, (g,g) at [kk][node]

    const int tid = threadIdx.x;

    // stage interleaved weights: sW[k*64+j] = (Ws[k][j], Wn[k][j])
    const float4* Ws4 = (const float4*)Wself;
    const float4* Wn4 = (const float4*)Wneigh;
    #pragma unroll
    for (int i = tid; i < DIM * DIM / 4; i += 256) {
        const float4 a = Ws4[i];
        const float4 b = Wn4[i];
        sW[4 * i + 0] = make_float2(a.x, b.x);
        sW[4 * i + 1] = make_float2(a.y, b.y);
        sW[4 * i + 2] = make_float2(a.z, b.z);
        sW[4 * i + 3] = make_float2(a.w, b.w);
    }

    // thread layout: warp spans 2 node-octets, 16 j-pairs
    const int jhalf = tid >> 7;           // 0/1 -> j offset 0 / 32
    const int grp   = (tid >> 4) & 7;     // node octet 0..7
    const int jp    = tid & 15;           // j-pair within half
    const int j     = jhalf * 32 + jp * 2;

    const int node0 = blockIdx.x * 64;
    const float4* in4 = (const float4*)in;

    unsigned long long av[8][2];
    #pragma unroll
    for (int m = 0; m < 8; m++) { av[m][0] = 0ull; av[m][1] = 0ull; }

    #pragma unroll
    for (int ph = 0; ph < 2; ph++) {
        __syncthreads();   // sgT reuse (also covers sW staging on ph=0)
        // stage 64 nodes x 32 k, duplicated (g,g), relu fused
        #pragma unroll
        for (int i = tid; i < 64 * 8; i += 256) {
            const int node = i & 63;
            const int q    = i >> 6;              // 0..7 -> k rows 4q..4q+3
            float4 v = make_float4(0.f, 0.f, 0.f, 0.f);
            if (node0 + node < N_NODES)
                v = in4[(size_t)(node0 + node) * 16 + ph * 8 + q];
            if (relu_in) {
                v.x = fmaxf(v.x, 0.f); v.y = fmaxf(v.y, 0.f);
                v.z = fmaxf(v.z, 0.f); v.w = fmaxf(v.w, 0.f);
            }
            sgT[(4 * q + 0) * DIM + node] = dup_f(v.x);
            sgT[(4 * q + 1) * DIM + node] = dup_f(v.y);
            sgT[(4 * q + 2) * DIM + node] = dup_f(v.z);
            sgT[(4 * q + 3) * DIM + node] = dup_f(v.w);
        }
        __syncthreads();

        #pragma unroll
        for (int kk = 0; kk < 32; kk++) {
            const int k = ph * 32 + kk;
            // (ws,wn) for j and j+1 : one LDS.128
            const ulonglong2 w = *(const ulonglong2*)(sW + k * DIM + j);
            const ulonglong2* gp = (const ulonglong2*)(sgT + kk * DIM + grp * 8);
            #pragma unroll
            for (int p = 0; p < 4; p++) {
                const ulonglong2 g = gp[p];        // 2 duplicated nodes
                fma2(av[2 * p][0],     g.x, w.x);
                fma2(av[2 * p][1],     g.x, w.y);
                fma2(av[2 * p + 1][0], g.y, w.x);
                fma2(av[2 * p + 1][1], g.y, w.y);
            }
        }
    }

    // epilogue: av[m][q] = (S, N) for node grp*8+m, column j+q
    const float2 b2 = *(const float2*)(bias + j);
    #pragma unroll
    for (int m = 0; m < 8; m++) {
        const int node = node0 + grp * 8 + m;
        if (node < N_NODES) {
            float2 s = make_float2(f_lo(av[m][0]) + b2.x, f_lo(av[m][1]) + b2.y);
            float2 n = make_float2(f_hi(av[m][0]),        f_hi(av[m][1]));
            *(float2*)(acc + (size_t)node * DIM + j) = s;
            *(float2*)(t   + (size_t)node * DIM + j) = n;
        }
    }
}

// ---------------------------------------------------------------------------
// K2: bucketed gather, high MLP.  out[n] = (relu?)( acc[n] + sum w_e*t[col_e] )
// ---------------------------------------------------------------------------
__global__ void __launch_bounds__(256) sage_gather(
    const float* __restrict__ t,
    const float* __restrict__ acc,
    float* __restrict__ out,
    int relu_out)
{
    const int node = blockIdx.x * 16 + (threadIdx.x >> 4);
    const int lane = threadIdx.x & 15;
    const int cnt  = min(g_cnt[node], CAP);

    const int2* cw = g_cw + (size_t)node * CAP;
    const float4* t4 = (const float4*)t;

    float4 s0 = make_float4(0.f, 0.f, 0.f, 0.f);
    float4 s1 = make_float4(0.f, 0.f, 0.f, 0.f);

    int k = 0;
    for (; k + 4 <= cnt; k += 4) {
        const int4 a = *(const int4*)(cw + k);
        const int4 b = *(const int4*)(cw + k + 2);
        const float4 v0 = __ldg(t4 + (size_t)a.x * 16 + lane);
        const float4 v1 = __ldg(t4 + (size_t)a.z * 16 + lane);
        const float4 v2 = __ldg(t4 + (size_t)b.x * 16 + lane);
        const float4 v3 = __ldg(t4 + (size_t)b.z * 16 + lane);
        const float w0 = __int_as_float(a.y);
        const float w1 = __int_as_float(a.w);
        const float w2 = __int_as_float(b.y);
        const float w3 = __int_as_float(b.w);
        s0.x = fmaf(w0, v0.x, s0.x); s0.y = fmaf(w0, v0.y, s0.y);
        s0.z = fmaf(w0, v0.z, s0.z); s0.w = fmaf(w0, v0.w, s0.w);
        s1.x = fmaf(w1, v1.x, s1.x); s1.y = fmaf(w1, v1.y, s1.y);
        s1.z = fmaf(w1, v1.z, s1.z); s1.w = fmaf(w1, v1.w, s1.w);
        s0.x = fmaf(w2, v2.x, s0.x); s0.y = fmaf(w2, v2.y, s0.y);
        s0.z = fmaf(w2, v2.z, s0.z); s0.w = fmaf(w2, v2.w, s0.w);
        s1.x = fmaf(w3, v3.x, s1.x); s1.y = fmaf(w3, v3.y, s1.y);
        s1.z = fmaf(w3, v3.z, s1.z); s1.w = fmaf(w3, v3.w, s1.w);
    }
    for (; k < cnt; k++) {
        const int2 c = cw[k];
        const float4 v = __ldg(t4 + (size_t)c.x * 16 + lane);
        const float w = __int_as_float(c.y);
        s0.x = fmaf(w, v.x, s0.x); s0.y = fmaf(w, v.y, s0.y);
        s0.z = fmaf(w, v.z, s0.z); s0.w = fmaf(w, v.w, s0.w);
    }

    float4 a = ((const float4*)acc)[(size_t)node * 16 + lane];
    a.x += s0.x + s1.x; a.y += s0.y + s1.y;
    a.z += s0.z + s1.z; a.w += s0.w + s1.w;
    if (relu_out) {
        a.x = fmaxf(a.x, 0.f); a.y = fmaxf(a.y, 0.f);
        a.z = fmaxf(a.z, 0.f); a.w = fmaxf(a.w, 0.f);
    }
    ((float4*)out)[(size_t)node * 16 + lane] = a;
}

// ---------------------------------------------------------------------------
extern "C" void kernel_launch(void* const* d_in, const int* in_sizes, int n_in,
                              void* d_out, int out_size)
{
    const float* x     = (const float*)d_in[0];   // [N, 64]
    const int*   ei    = (const int*)  d_in[1];   // [2, E]
    const float* ew    = (const float*)d_in[2];   // [E]
    const float* Wself = (const float*)d_in[3];   // [3, 64, 64]
    const float* Wngh  = (const float*)d_in[4];   // [3, 64, 64]
    const float* bias  = (const float*)d_in[5];   // [3, 64]
    float* out = (float*)d_out;                   // [N, 64]

    const int* row = ei;            // targets (segment ids)
    const int* col = ei + N_EDGES;  // sources

    float *t_ptr, *acc_ptr;
    void *cnt_p;
    cudaGetSymbolAddress((void**)&t_ptr,   g_t);
    cudaGetSymbolAddress((void**)&acc_ptr, g_acc);
    cudaGetSymbolAddress(&cnt_p, g_cnt);

    // ---- bucketed edge build (once per call, reused by all 3 layers) ----
    cudaMemsetAsync(cnt_p, 0, N_NODES * sizeof(int));
    k_fill<<<(N_EDGES + 255) / 256, 256>>>(row, col, ew);

    const int GEMM_BLOCKS   = (N_NODES + 63) / 64;   // 1563
    const int GATHER_BLOCKS = N_NODES / 16;          // 6250 (exact)

    // layer 0
    sage_gemm<<<GEMM_BLOCKS, 256>>>(x, acc_ptr, t_ptr, Wself, Wngh, bias, 0);
    sage_gather<<<GATHER_BLOCKS, 256>>>(t_ptr, acc_ptr, acc_ptr, 0);

    // layer 1 (relu fused into GEMM input staging)
    sage_gemm<<<GEMM_BLOCKS, 256>>>(acc_ptr, acc_ptr, t_ptr,
                                    Wself + DIM * DIM, Wngh + DIM * DIM, bias + DIM, 1);
    sage_gather<<<GATHER_BLOCKS, 256>>>(t_ptr, acc_ptr, acc_ptr, 0);

    // layer 2 (relu fused into gather, writes d_out directly)
    sage_gemm<<<GEMM_BLOCKS, 256>>>(acc_ptr, acc_ptr, t_ptr,
                                    Wself + 2 * DIM * DIM, Wngh + 2 * DIM * DIM, bias + 2 * DIM, 1);
    sage_gather<<<GATHER_BLOCKS, 256>>>(t_ptr, acc_ptr, out, 1);
}

// round 7
// speedup vs baseline: 1.4223x; 1.4223x over previous
#include <cuda_runtime.h>
#include <cuda_bf16.h>
#include <cstdint>

#define N_NODES 100000
#define DIM 64
#define N_EDGES 1200000
#define CAP 64
#define M_TILE 128
#define N_TILES ((N_NODES + M_TILE - 1) / M_TILE)   // 782
#define GEMM_GRID 152

// ---- scratch (__device__ globals: allocation-free rule) --------------------
__device__ float g_t[N_NODES * DIM];
__device__ float g_acc[N_NODES * DIM];
__device__ int   g_cnt[N_NODES];
__device__ int2  g_cw[(size_t)N_NODES * CAP];
__device__ uint2 g_wbf[3 * 2 * 4 * 16 * 32];   // [layer][split][q][n8][lane] B frags

// ---------------------------------------------------------------------------
__device__ __forceinline__ uint32_t pack_bf2(float a, float b)
{
    __nv_bfloat162 h = __floats2bfloat162_rn(a, b);
    return *(uint32_t*)&h;
}

// ---------------------------------------------------------------------------
// Weight fragment prep (once per call): B[k][n] with n<64 -> Ws, else Wn.
// Fragment layout of mma.sync m16n8k16 .row.col B operand:
//   b0 = {B[k0+tg*2][n], B[k0+tg*2+1][n]},  b1 = same at k0+8.  n = n8*8 + g.
// ---------------------------------------------------------------------------
__global__ void k_wprep(const float* __restrict__ Ws, const float* __restrict__ Wn)
{
    const int idx = blockIdx.x * 256 + threadIdx.x;
    if (idx >= 3 * 2 * 4 * 16 * 32) return;
    const int lane = idx & 31;
    const int n8   = (idx >> 5) & 15;
    const int q    = (idx >> 9) & 3;
    const int s    = (idx >> 11) & 1;
    const int l    = idx >> 12;
    const int g  = lane >> 2, tg = lane & 3;
    const int n  = n8 * 8 + g;
    const int k0 = q * 16;

    const float* W = (n < DIM) ? (Ws + l * DIM * DIM) : (Wn + l * DIM * DIM - DIM);
    // W[k][n] = W[k*64 + n] (the -DIM above folds the j-64)
    float v[4];
    v[0] = W[(k0 + tg * 2) * DIM + n];
    v[1] = W[(k0 + tg * 2 + 1) * DIM + n];
    v[2] = W[(k0 + 8 + tg * 2) * DIM + n];
    v[3] = W[(k0 + 8 + tg * 2 + 1) * DIM + n];
    if (s == 1) {   // lo split
        #pragma unroll
        for (int i = 0; i < 4; i++)
            v[i] = v[i] - __bfloat162float(__float2bfloat16(v[i]));
    }
    g_wbf[idx] = make_uint2(pack_bf2(v[0], v[1]), pack_bf2(v[2], v[3]));
}

// ---------------------------------------------------------------------------
// bucketed edge build
// ---------------------------------------------------------------------------
__global__ void k_fill(const int* __restrict__ row, const int* __restrict__ col,
                       const float* __restrict__ ew)
{
    int e = blockIdx.x * blockDim.x + threadIdx.x;
    if (e >= N_EDGES) return;
    const int r = row[e];
    const int p = atomicAdd(&g_cnt[r], 1);
    if (p < CAP)
        g_cw[(size_t)r * CAP + p] = make_int2(col[e], __float_as_int(ew[e]));
}

// ---------------------------------------------------------------------------
__device__ __forceinline__ void mma_bf16(float* c, const uint32_t* a, uint2 b)
{
    asm volatile(
        "mma.sync.aligned.m16n8k16.row.col.f32.bf16.bf16.f32 "
        "{%0,%1,%2,%3}, {%4,%5,%6,%7}, {%8,%9}, {%0,%1,%2,%3};"
        : "+f"(c[0]), "+f"(c[1]), "+f"(c[2]), "+f"(c[3])
        : "r"(a[0]), "r"(a[1]), "r"(a[2]), "r"(a[3]), "r"(b.x), "r"(b.y));
}
__device__ __forceinline__ void ldsm4(uint32_t* a, uint32_t addr)
{
    asm volatile("ldmatrix.sync.aligned.m8n8.x4.shared.b16 {%0,%1,%2,%3}, [%4];"
                 : "=r"(a[0]), "=r"(a[1]), "=r"(a[2]), "=r"(a[3]) : "r"(addr));
}

#define SA_PITCH 144                 // 64 bf16 (128B) + 16B pad -> conflict-free
#define SA_SPLIT (M_TILE * SA_PITCH) // 18432B per split

// ---------------------------------------------------------------------------
// K1: persistent tensor-core dual GEMM (bf16 3-split via mma.sync).
//   acc[m,0:64] = relu?(in)@Ws + b ; t[m,0:64] = relu?(in)@Wn
// 256 thr = 8 warps: wm = wid>>2 (m-half, 64 nodes), wn = wid&3 (n-quarter, 32 j).
// B frags live in registers for the whole kernel; A via SMEM + ldmatrix.
// ---------------------------------------------------------------------------
__global__ void __launch_bounds__(256, 1) sage_gemm_mma(
    const float* __restrict__ in,
    float* __restrict__ acc,
    float* __restrict__ t,
    const uint2* __restrict__ wb,
    const float* __restrict__ bias,
    int relu_in)
{
    __shared__ __align__(16) unsigned char sA[2 * SA_SPLIT];

    const int tid  = threadIdx.x;
    const int wid  = tid >> 5;
    const int lane = tid & 31;
    const int wm   = wid >> 2;        // 0..1
    const int wn   = wid & 3;         // 0..3
    const int g    = lane >> 2;
    const int tg   = lane & 3;

    // ---- preload B fragments (hi, lo) into registers ----
    uint2 bw[2][4][4];                // [split][q][n8]
    #pragma unroll
    for (int s = 0; s < 2; s++)
        #pragma unroll
        for (int q = 0; q < 4; q++)
            #pragma unroll
            for (int n8 = 0; n8 < 4; n8++)
                bw[s][q][n8] = wb[(((s * 4 + q) * 16) + wn * 4 + n8) * 32 + lane];

    float2 bias2[4];
    if (wn < 2) {
        #pragma unroll
        for (int n8 = 0; n8 < 4; n8++)
            bias2[n8] = *(const float2*)(bias + wn * 32 + n8 * 8 + tg * 2);
    }

    // ldmatrix per-lane base address
    uint32_t sa_base;
    asm("{ .reg .u64 u; cvta.to.shared.u64 u, %1; cvt.u32.u64 %0, u; }"
        : "=r"(sa_base) : "l"(sA));
    const int r    = lane & 7;
    const int row8 = ((lane >> 3) & 1) * 8;
    const int koff = (lane >> 4) * 16;             // +8 cols -> +16B
    const uint32_t abase = sa_base + (wm * 64 + row8 + r) * SA_PITCH + koff;

    const float4* in4 = (const float4*)in;

    for (int tile = blockIdx.x; tile < N_TILES; tile += gridDim.x) {
        const int node0 = tile * M_TILE;

        // ---- stage A: relu + bf16 hi/lo split, [node][k] rows, pitch 144B ----
        #pragma unroll
        for (int i = tid; i < M_TILE * (DIM / 4); i += 256) {
            const int node = i >> 4;
            const int kq   = i & 15;
            float4 v = make_float4(0.f, 0.f, 0.f, 0.f);
            if (node0 + node < N_NODES)
                v = in4[(size_t)(node0 + node) * (DIM / 4) + kq];
            if (relu_in) {
                v.x = fmaxf(v.x, 0.f); v.y = fmaxf(v.y, 0.f);
                v.z = fmaxf(v.z, 0.f); v.w = fmaxf(v.w, 0.f);
            }
            float hx = __bfloat162float(__float2bfloat16(v.x));
            float hy = __bfloat162float(__float2bfloat16(v.y));
            float hz = __bfloat162float(__float2bfloat16(v.z));
            float hw = __bfloat162float(__float2bfloat16(v.w));
            uint2 hi = make_uint2(pack_bf2(v.x, v.y), pack_bf2(v.z, v.w));
            uint2 lo = make_uint2(pack_bf2(v.x - hx, v.y - hy),
                                  pack_bf2(v.z - hz, v.w - hw));
            *(uint2*)(sA + node * SA_PITCH + kq * 8)            = hi;
            *(uint2*)(sA + SA_SPLIT + node * SA_PITCH + kq * 8) = lo;
        }
        __syncthreads();

        // ---- MMA mainloop ----
        float c[4][4][4];
        #pragma unroll
        for (int mf = 0; mf < 4; mf++)
            #pragma unroll
            for (int n8 = 0; n8 < 4; n8++)
                #pragma unroll
                for (int e = 0; e < 4; e++) c[mf][n8][e] = 0.f;

        #pragma unroll
        for (int q = 0; q < 4; q++) {
            uint32_t ah[4][4], al[4][4];
            #pragma unroll
            for (int mf = 0; mf < 4; mf++) {
                ldsm4(ah[mf], abase + mf * 16 * SA_PITCH + q * 32);
                ldsm4(al[mf], abase + SA_SPLIT + mf * 16 * SA_PITCH + q * 32);
            }
            #pragma unroll
            for (int n8 = 0; n8 < 4; n8++) {
                #pragma unroll
                for (int mf = 0; mf < 4; mf++) {
                    mma_bf16(c[mf][n8], ah[mf], bw[0][q][n8]);  // hi*hi
                    mma_bf16(c[mf][n8], al[mf], bw[0][q][n8]);  // lo*hi
                    mma_bf16(c[mf][n8], ah[mf], bw[1][q][n8]);  // hi*lo
                }
            }
        }

        // ---- epilogue ----
        const bool self = (wn < 2);
        float* basep = self ? acc : t;
        #pragma unroll
        for (int n8 = 0; n8 < 4; n8++) {
            const int jj   = wn * 32 + n8 * 8 + tg * 2;
            const int jloc = self ? jj : (jj - 64);
            const float bx = self ? bias2[n8].x : 0.f;
            const float by = self ? bias2[n8].y : 0.f;
            #pragma unroll
            for (int mf = 0; mf < 4; mf++) {
                const int nd = node0 + wm * 64 + mf * 16 + g;
                if (nd < N_NODES) {
                    float2 v = make_float2(c[mf][n8][0] + bx, c[mf][n8][1] + by);
                    *(float2*)(basep + (size_t)nd * DIM + jloc) = v;
                }
                if (nd + 8 < N_NODES) {
                    float2 v = make_float2(c[mf][n8][2] + bx, c[mf][n8][3] + by);
                    *(float2*)(basep + (size_t)(nd + 8) * DIM + jloc) = v;
                }
            }
        }
        __syncthreads();
    }
}

// ---------------------------------------------------------------------------
// K2: bucketed gather (unchanged from R4).
// ---------------------------------------------------------------------------
__global__ void __launch_bounds__(256) sage_gather(
    const float* __restrict__ t,
    const float* __restrict__ acc,
    float* __restrict__ out,
    int relu_out)
{
    const int node = blockIdx.x * 16 + (threadIdx.x >> 4);
    const int lane = threadIdx.x & 15;
    const int cnt  = min(g_cnt[node], CAP);

    const int2* cw = g_cw + (size_t)node * CAP;
    const float4* t4 = (const float4*)t;

    float4 s0 = make_float4(0.f, 0.f, 0.f, 0.f);
    float4 s1 = make_float4(0.f, 0.f, 0.f, 0.f);

    int k = 0;
    for (; k + 4 <= cnt; k += 4) {
        const int4 a = *(const int4*)(cw + k);
        const int4 b = *(const int4*)(cw + k + 2);
        const float4 v0 = __ldg(t4 + (size_t)a.x * 16 + lane);
        const float4 v1 = __ldg(t4 + (size_t)a.z * 16 + lane);
        const float4 v2 = __ldg(t4 + (size_t)b.x * 16 + lane);
        const float4 v3 = __ldg(t4 + (size_t)b.z * 16 + lane);
        const float w0 = __int_as_float(a.y);
        const float w1 = __int_as_float(a.w);
        const float w2 = __int_as_float(b.y);
        const float w3 = __int_as_float(b.w);
        s0.x = fmaf(w0, v0.x, s0.x); s0.y = fmaf(w0, v0.y, s0.y);
        s0.z = fmaf(w0, v0.z, s0.z); s0.w = fmaf(w0, v0.w, s0.w);
        s1.x = fmaf(w1, v1.x, s1.x); s1.y = fmaf(w1, v1.y, s1.y);
        s1.z = fmaf(w1, v1.z, s1.z); s1.w = fmaf(w1, v1.w, s1.w);
        s0.x = fmaf(w2, v2.x, s0.x); s0.y = fmaf(w2, v2.y, s0.y);
        s0.z = fmaf(w2, v2.z, s0.z); s0.w = fmaf(w2, v2.w, s0.w);
        s1.x = fmaf(w3, v3.x, s1.x); s1.y = fmaf(w3, v3.y, s1.y);
        s1.z = fmaf(w3, v3.z, s1.z); s1.w = fmaf(w3, v3.w, s1.w);
    }
    for (; k < cnt; k++) {
        const int2 c = cw[k];
        const float4 v = __ldg(t4 + (size_t)c.x * 16 + lane);
        const float w = __int_as_float(c.y);
        s0.x = fmaf(w, v.x, s0.x); s0.y = fmaf(w, v.y, s0.y);
        s0.z = fmaf(w, v.z, s0.z); s0.w = fmaf(w, v.w, s0.w);
    }

    float4 a = ((const float4*)acc)[(size_t)node * 16 + lane];
    a.x += s0.x + s1.x; a.y += s0.y + s1.y;
    a.z += s0.z + s1.z; a.w += s0.w + s1.w;
    if (relu_out) {
        a.x = fmaxf(a.x, 0.f); a.y = fmaxf(a.y, 0.f);
        a.z = fmaxf(a.z, 0.f); a.w = fmaxf(a.w, 0.f);
    }
    ((float4*)out)[(size_t)node * 16 + lane] = a;
}

// ---------------------------------------------------------------------------
extern "C" void kernel_launch(void* const* d_in, const int* in_sizes, int n_in,
                              void* d_out, int out_size)
{
    const float* x     = (const float*)d_in[0];
    const int*   ei    = (const int*)  d_in[1];
    const float* ew    = (const float*)d_in[2];
    const float* Wself = (const float*)d_in[3];
    const float* Wngh  = (const float*)d_in[4];
    const float* bias  = (const float*)d_in[5];
    float* out = (float*)d_out;

    const int* row = ei;
    const int* col = ei + N_EDGES;

    float *t_ptr, *acc_ptr;
    uint2* wb_ptr;
    void *cnt_p;
    cudaGetSymbolAddress((void**)&t_ptr,   g_t);
    cudaGetSymbolAddress((void**)&acc_ptr, g_acc);
    cudaGetSymbolAddress((void**)&wb_ptr,  g_wbf);
    cudaGetSymbolAddress(&cnt_p, g_cnt);

    // once-per-call prep
    cudaMemsetAsync(cnt_p, 0, N_NODES * sizeof(int));
    k_wprep<<<(3 * 2 * 4 * 16 * 32 + 255) / 256, 256>>>(Wself, Wngh);
    k_fill<<<(N_EDGES + 255) / 256, 256>>>(row, col, ew);

    const int GATHER_BLOCKS = N_NODES / 16;   // 6250
    const int WB_L = 2 * 4 * 16 * 32;         // 4096 uint2 per layer

    // layer 0
    sage_gemm_mma<<<GEMM_GRID, 256>>>(x, acc_ptr, t_ptr, wb_ptr, bias, 0);
    sage_gather<<<GATHER_BLOCKS, 256>>>(t_ptr, acc_ptr, acc_ptr, 0);

    // layer 1
    sage_gemm_mma<<<GEMM_GRID, 256>>>(acc_ptr, acc_ptr, t_ptr,
                                      wb_ptr + WB_L, bias + DIM, 1);
    sage_gather<<<GATHER_BLOCKS, 256>>>(t_ptr, acc_ptr, acc_ptr, 0);

    // layer 2 (relu fused into gather, writes d_out)
    sage_gemm_mma<<<GEMM_GRID, 256>>>(acc_ptr, acc_ptr, t_ptr,
                                      wb_ptr + 2 * WB_L, bias + 2 * DIM, 1);
    sage_gather<<<GATHER_BLOCKS, 256>>>(t_ptr, acc_ptr, out, 1);
}